// round 12
// baseline (speedup 1.0000x reference)
#include <cuda_runtime.h>
#include <math.h>

#define NB     64
#define LSEQ   256
#define LA     8
#define EMBED  300
#define HID    384
#define D3     3072   // 2 * 4 * HID (both directions' gate columns)
#define DF     768    // 2 * HID
#define NCLS   3

// ---------------- scratch (device globals; allocation is forbidden) ----------
__device__ float g_xg_s[(size_t)LSEQ * D3 * NB];   // [t][col][n]
__device__ float g_xg_a[(size_t)LA   * D3 * NB];   // [t][col][n]
__device__ float g_feat [(size_t)LSEQ * DF * NB];  // [t][d][n]
__device__ float g_afeat[(size_t)LA   * DF * NB];  // [t][d][n]
__device__ float g_aspv[DF * NB];                  // [d][n]
__device__ float g_dot[LSEQ * NB];                 // [t][n]
__device__ float g_att[LSEQ * NB];                 // [t][n]
__device__ float g_pooled[NB * DF];                // [n][d]
__device__ float g_x1[NB * DF];
__device__ float g_x2[NB * DF];
__device__ float g_logit[NB * NCLS];
// barrier state: group counters (8 per dir), root counters, generation —
// every counter on its own 128B line to avoid L2-atom serialization.
__device__ __align__(128) unsigned g_cntg[2 * 8 * 32];
__device__ __align__(128) unsigned g_cntr[2 * 32];
__device__ __align__(128) unsigned g_gen2[2 * 32];

// ---------------- f32x2 packed helpers (Blackwell FFMA2 / FADD2) -------------
typedef unsigned long long ull;

__device__ __forceinline__ ull pack2(float x, float y) {
    ull r; asm("mov.b64 %0, {%1,%2};" : "=l"(r) : "f"(x), "f"(y)); return r;
}
__device__ __forceinline__ ull fma2(ull a, ull b, ull c) {
    ull d; asm("fma.rn.f32x2 %0, %1, %2, %3;" : "=l"(d) : "l"(a), "l"(b), "l"(c));
    return d;
}
__device__ __forceinline__ ull add2(ull a, ull b) {
    ull d; asm("add.rn.f32x2 %0, %1, %2;" : "=l"(d) : "l"(a), "l"(b));
    return d;
}
__device__ __forceinline__ void unpack2(ull v, float& lo, float& hi) {
    asm("mov.b64 {%0,%1}, %2;" : "=f"(lo), "=f"(hi) : "l"(v));
}

__device__ __forceinline__ float sigm(float x) { return 1.f / (1.f + __expf(-x)); }
__device__ __forceinline__ float ftanh(float x) { return 2.f / (1.f + __expf(-2.f * x)) - 1.f; }

// ---------------- bulk-copy + mbarrier helpers -------------------------------
__device__ __forceinline__ void mbar_init(unsigned mbar, unsigned count) {
    asm volatile("mbarrier.init.shared.b64 [%0], %1;" :: "r"(mbar), "r"(count) : "memory");
}
__device__ __forceinline__ void mbar_expect_tx(unsigned mbar, unsigned bytes) {
    asm volatile("mbarrier.arrive.expect_tx.shared.b64 _, [%0], %1;"
                 :: "r"(mbar), "r"(bytes) : "memory");
}
__device__ __forceinline__ void bulk_g2s(unsigned dst, const void* src,
                                         unsigned bytes, unsigned mbar) {
    asm volatile(
        "cp.async.bulk.shared::cluster.global.mbarrier::complete_tx::bytes "
        "[%0], [%1], %2, [%3];"
        :: "r"(dst), "l"(src), "r"(bytes), "r"(mbar) : "memory");
}
__device__ __forceinline__ void mbar_wait(unsigned mbar, unsigned par) {
    asm volatile(
        "{\n\t.reg .pred p;\n\t"
        "LAB_WAIT_%=:\n\t"
        "mbarrier.try_wait.parity.shared::cta.b64 p, [%0], %1;\n\t"
        "@!p bra LAB_WAIT_%=;\n\t"
        "}" :: "r"(mbar), "r"(par) : "memory");
}

// =============================================================================
// K1: fused embedding-gather + input-projection GEMM (both sequences)
// =============================================================================
#define SMEM_XG (60*132*8 + 60*68*4 + 256)

__global__ __launch_bounds__(256) void k_gemm_xg(
    const int* __restrict__ sent, const int* __restrict__ asp,
    const float* __restrict__ emb,
    const float* __restrict__ wf,  const float* __restrict__ wb,
    const float* __restrict__ bif, const float* __restrict__ bhf,
    const float* __restrict__ bib, const float* __restrict__ bhb,
    float* __restrict__ xg_s, float* __restrict__ xg_a)
{
    extern __shared__ char smc[];
    ull*   Bsu = (ull*)smc;                       // [e][c] dup pairs, stride 132
    float* As  = (float*)(smc + 60 * 132 * 8);    // [e][n] stride 68
    int*   tk  = (int*)(smc + 60 * 132 * 8 + 60 * 68 * 4);

    int t = blockIdx.x;
    const int* tok; int T; float* xg;
    if (t < LSEQ) { tok = sent; T = LSEQ; xg = xg_s; }
    else          { t -= LSEQ; tok = asp; T = LA; xg = xg_a; }

    const int cbase = blockIdx.y * 128;
    const int tid   = threadIdx.x;
    const int dir   = (cbase >= 1536) ? 1 : 0;
    const float* W  = dir ? wb  : wf;
    const float* bi = dir ? bib : bif;
    const float* bh = dir ? bhb : bhf;
    const int cl    = cbase - dir * 1536;

    if (tid < 64) tk[tid] = tok[tid * T + t];

    const int tx = tid & 15, ty = tid >> 4;
    const int n0 = tx * 4,   c0 = ty * 8;

    ull acc[8][2];
    #pragma unroll
    for (int i = 0; i < 8; i++) {
        float b = bi[cl + c0 + i] + bh[cl + c0 + i];
        acc[i][0] = pack2(b, b);
        acc[i][1] = acc[i][0];
    }

    for (int kb = 0; kb < 5; kb++) {
        const int e0 = kb * 60;
        __syncthreads();
        for (int f = tid; f < 64 * 60; f += 256) {
            int n = f / 60, e = f % 60;
            As[e * 68 + n] = emb[(size_t)tk[n] * EMBED + e0 + e];
        }
        for (int f = tid; f < 128 * 60; f += 256) {
            int c = f / 60, e = f % 60;
            float w = W[(size_t)(cl + c) * EMBED + e0 + e];
            Bsu[e * 132 + c] = pack2(w, w);
        }
        __syncthreads();
        #pragma unroll 4
        for (int e = 0; e < 60; e++) {
            ulonglong2 a2 = *(const ulonglong2*)&As[e * 68 + n0];
            ulonglong2 b0 = *(const ulonglong2*)&Bsu[e * 132 + c0];
            ulonglong2 b1 = *(const ulonglong2*)&Bsu[e * 132 + c0 + 2];
            ulonglong2 b2 = *(const ulonglong2*)&Bsu[e * 132 + c0 + 4];
            ulonglong2 b3 = *(const ulonglong2*)&Bsu[e * 132 + c0 + 6];
            acc[0][0] = fma2(b0.x, a2.x, acc[0][0]); acc[0][1] = fma2(b0.x, a2.y, acc[0][1]);
            acc[1][0] = fma2(b0.y, a2.x, acc[1][0]); acc[1][1] = fma2(b0.y, a2.y, acc[1][1]);
            acc[2][0] = fma2(b1.x, a2.x, acc[2][0]); acc[2][1] = fma2(b1.x, a2.y, acc[2][1]);
            acc[3][0] = fma2(b1.y, a2.x, acc[3][0]); acc[3][1] = fma2(b1.y, a2.y, acc[3][1]);
            acc[4][0] = fma2(b2.x, a2.x, acc[4][0]); acc[4][1] = fma2(b2.x, a2.y, acc[4][1]);
            acc[5][0] = fma2(b2.y, a2.x, acc[5][0]); acc[5][1] = fma2(b2.y, a2.y, acc[5][1]);
            acc[6][0] = fma2(b3.x, a2.x, acc[6][0]); acc[6][1] = fma2(b3.x, a2.y, acc[6][1]);
            acc[7][0] = fma2(b3.y, a2.x, acc[7][0]); acc[7][1] = fma2(b3.y, a2.y, acc[7][1]);
        }
    }

    size_t base = ((size_t)t * D3 + cbase + c0) * NB + n0;
    #pragma unroll
    for (int i = 0; i < 8; i++)
        *(ulonglong2*)&xg[base + (size_t)i * NB] = make_ulonglong2(acc[i][0], acc[i][1]);
}

// no-op launches: shift the ncu -s 5 -c 1 capture window onto k_lstm
__global__ void k_nop() {}

// =============================================================================
// K2: persistent BiLSTM. 128 blocks (64 fwd + 64 bwd), 1/SM, 256 threads.
//   K-split across warps (warp w owns k in [48w,48w+48), stages its own 12 KB
//   chunk with one cp.async.bulk). Tree barrier: 8x8 atomics per dir + root +
//   gen; release detected PER WARP at the top of each step (wait/bump strictly
//   1:1 across the whole kernel -> race-free g_cur arithmetic).
// =============================================================================
#define GSW 1632   // per-warp gS slab: 24 rows * 68 floats
#define MBAR_OFF (384*24*8 + 384*64*4 + 8*GSW*4 + 384*4)      // 225,792
#define SMEM_LSTM (MBAR_OFF + 64)                             // + 8 mbarriers

__global__ __launch_bounds__(256) void k_lstm(
    const float* __restrict__ xg_s, float* __restrict__ feat_s,
    const float* __restrict__ xg_a, float* __restrict__ feat_a,
    const float* __restrict__ whf, const float* __restrict__ whb)
{
    extern __shared__ char smc[];
    ull*   wD = (ull*)smc;                               // [k][r] dup pairs, stride 24
    float* hS = (float*)(smc + 384 * 24 * 8);            // [k][n]
    float* gS = hS + 384 * 64;                           // [w][r][n] stride 68
    float* cS = gS + 8 * GSW;                            // [u][n] (u*64+n)

    const int b   = blockIdx.x;
    const int dir = b >> 6;
    const int ub  = (b & 63) * 6;
    const int grp = (b & 63) >> 3;
    const float* whh = dir ? whb : whf;
    const int tid = threadIdx.x;

    volatile unsigned* cg = &g_cntg[(dir * 8 + grp) * 32];
    volatile unsigned* cr = &g_cntr[dir * 32];
    volatile unsigned* gv = &g_gen2[dir * 32];

    const unsigned smem_base = (unsigned)__cvta_generic_to_shared(smc);
    const unsigned mbar0 = smem_base + MBAR_OFF;
    if (tid < 8) mbar_init(mbar0 + tid * 8u, 1u);

    // persistent dup-weight load: 24 gate-rows x 384 k
    for (int idx = tid; idx < 24 * 384; idx += 256) {
        int k = idx / 24, r = idx % 24;
        int gt = r / 6, u = r % 6;
        float w = whh[(size_t)(gt * 384 + ub + u) * HID + k];
        wD[k * 24 + r] = pack2(w, w);
    }

    const int w    = tid >> 5;            // warp id = k-chunk
    const int lane = tid & 31;
    const int rg   = lane >> 3;           // row-group (gate): rows rg*6 .. rg*6+5
    const int nn   = (lane & 7) * 8;      // batch base: 8 n per thread
    const int kbase = w * 48;
    const unsigned hS_u = (unsigned)__cvta_generic_to_shared(hS);
    const unsigned hS_chunk = hS_u + (unsigned)kbase * 64u * 4u;   // w * 12288
    const unsigned my_mbar  = mbar0 + (unsigned)w * 8u;

    unsigned par = 0;            // mbarrier phase parity
    unsigned g_cur = *gv;        // stable: prior launch fully finished

    for (int phase = 0; phase < 2; phase++) {
        const int T = phase ? LA : LSEQ;
        const float* __restrict__ xg   = phase ? xg_a   : xg_s;
        float* __restrict__       feat = phase ? feat_a : feat_s;

        __syncthreads();
        for (int idx = tid; idx < 384; idx += 256) cS[idx] = 0.f;
        __syncthreads();

        // prefetch xg for step 0 (only warp 0 seeds xg into its partials)
        ull nxt[6][4];
        if (w == 0) {
            const int t0 = dir ? (T - 1) : 0;
            #pragma unroll
            for (int q = 0; q < 6; q++) {
                const float* p = &xg[((size_t)t0 * D3 + dir * 1536 + rg * 384 + ub + q) * NB + nn];
                ulonglong2 v0 = *(const ulonglong2*)p;
                ulonglong2 v1 = *(const ulonglong2*)(p + 4);
                nxt[q][0] = v0.x; nxt[q][1] = v0.y; nxt[q][2] = v1.x; nxt[q][3] = v1.y;
            }
        }

        for (int s = 0; s < T; s++) {
            const int t = dir ? (T - 1 - s) : s;

            // 0) per-warp release wait (every global step except the first)
            if (!(phase == 0 && s == 0)) {
                if (lane == 0) {
                    while (*gv == g_cur) { }
                }
                __syncwarp();
                g_cur++;
            }

            // 1) ONE bulk copy for this warp's 48-k h chunk (12 KB)
            if (s > 0) {
                const int tp = dir ? (t + 1) : (t - 1);
                const float* src = &feat[((size_t)tp * DF + dir * HID + kbase) * NB];
                if (lane == 0) {
                    mbar_expect_tx(my_mbar, 12288u);
                    bulk_g2s(hS_chunk, src, 12288u, my_mbar);
                }
            }

            ull acc[6][4];
            if (w == 0) {
                #pragma unroll
                for (int q = 0; q < 6; q++)
                    #pragma unroll
                    for (int j = 0; j < 4; j++) acc[q][j] = nxt[q][j];
            } else {
                #pragma unroll
                for (int q = 0; q < 6; q++)
                    #pragma unroll
                    for (int j = 0; j < 4; j++) acc[q][j] = 0ull;
            }

            // 2) wait own chunk, then gate GEMM (warp-local dependency only)
            if (s > 0) {
                mbar_wait(my_mbar, par);
                par ^= 1u;
                __syncwarp();
                #pragma unroll 4
                for (int kk = 0; kk < 48; kk++) {
                    const int k = kbase + kk;
                    ulonglong2 h0 = *(const ulonglong2*)&hS[k * 64 + nn];
                    ulonglong2 h1 = *(const ulonglong2*)&hS[k * 64 + nn + 4];
                    ulonglong2 wa = *(const ulonglong2*)&wD[k * 24 + rg * 6];
                    ulonglong2 wb2 = *(const ulonglong2*)&wD[k * 24 + rg * 6 + 2];
                    ulonglong2 wc2 = *(const ulonglong2*)&wD[k * 24 + rg * 6 + 4];
                    acc[0][0] = fma2(wa.x, h0.x, acc[0][0]);
                    acc[0][1] = fma2(wa.x, h0.y, acc[0][1]);
                    acc[0][2] = fma2(wa.x, h1.x, acc[0][2]);
                    acc[0][3] = fma2(wa.x, h1.y, acc[0][3]);
                    acc[1][0] = fma2(wa.y, h0.x, acc[1][0]);
                    acc[1][1] = fma2(wa.y, h0.y, acc[1][1]);
                    acc[1][2] = fma2(wa.y, h1.x, acc[1][2]);
                    acc[1][3] = fma2(wa.y, h1.y, acc[1][3]);
                    acc[2][0] = fma2(wb2.x, h0.x, acc[2][0]);
                    acc[2][1] = fma2(wb2.x, h0.y, acc[2][1]);
                    acc[2][2] = fma2(wb2.x, h1.x, acc[2][2]);
                    acc[2][3] = fma2(wb2.x, h1.y, acc[2][3]);
                    acc[3][0] = fma2(wb2.y, h0.x, acc[3][0]);
                    acc[3][1] = fma2(wb2.y, h0.y, acc[3][1]);
                    acc[3][2] = fma2(wb2.y, h1.x, acc[3][2]);
                    acc[3][3] = fma2(wb2.y, h1.y, acc[3][3]);
                    acc[4][0] = fma2(wc2.x, h0.x, acc[4][0]);
                    acc[4][1] = fma2(wc2.x, h0.y, acc[4][1]);
                    acc[4][2] = fma2(wc2.x, h1.x, acc[4][2]);
                    acc[4][3] = fma2(wc2.x, h1.y, acc[4][3]);
                    acc[5][0] = fma2(wc2.y, h0.x, acc[5][0]);
                    acc[5][1] = fma2(wc2.y, h0.y, acc[5][1]);
                    acc[5][2] = fma2(wc2.y, h1.x, acc[5][2]);
                    acc[5][3] = fma2(wc2.y, h1.y, acc[5][3]);
                }
            }

            // partials -> this warp's gS slab
            #pragma unroll
            for (int q = 0; q < 6; q++) {
                float* gr = &gS[w * GSW + (rg * 6 + q) * 68 + nn];
                *(ulonglong2*)gr       = make_ulonglong2(acc[q][0], acc[q][1]);
                *(ulonglong2*)(gr + 4) = make_ulonglong2(acc[q][2], acc[q][3]);
            }
            __syncthreads();

            // 3) reduce 8 warp-partials (f32x2), activations, h write.
            if (tid < 192) {
                int u = tid >> 5, n0 = (tid & 31) * 2;
                ull vi = 0, vf = 0, vg = 0, vo = 0;
                #pragma unroll
                for (int ww = 0; ww < 8; ww++) {
                    const float* gw = gS + ww * GSW;
                    vi = add2(vi, *(const ull*)&gw[(0 * 6 + u) * 68 + n0]);
                    vf = add2(vf, *(const ull*)&gw[(1 * 6 + u) * 68 + n0]);
                    vg = add2(vg, *(const ull*)&gw[(2 * 6 + u) * 68 + n0]);
                    vo = add2(vo, *(const ull*)&gw[(3 * 6 + u) * 68 + n0]);
                }
                float gi0, gi1, gf0, gf1, gg0, gg1, go0, go1;
                unpack2(vi, gi0, gi1); unpack2(vf, gf0, gf1);
                unpack2(vg, gg0, gg1); unpack2(vo, go0, go1);
                float c0 = sigm(gf0) * cS[u * 64 + n0]     + sigm(gi0) * ftanh(gg0);
                float c1 = sigm(gf1) * cS[u * 64 + n0 + 1] + sigm(gi1) * ftanh(gg1);
                cS[u * 64 + n0]     = c0;
                cS[u * 64 + n0 + 1] = c1;
                ull hv = pack2(sigm(go0) * ftanh(c0), sigm(go1) * ftanh(c1));
                __stcg((ull*)&feat[((size_t)t * DF + dir * HID + ub + u) * NB + n0], hv);
            }

            // 4) prefetch xg for next step (warp 0; hides LDG under barrier)
            if (w == 0 && s + 1 < T) {
                const int tn = dir ? (T - 2 - s) : (s + 1);
                #pragma unroll
                for (int q = 0; q < 6; q++) {
                    const float* p = &xg[((size_t)tn * D3 + dir * 1536 + rg * 384 + ub + q) * NB + nn];
                    ulonglong2 v0 = *(const ulonglong2*)p;
                    ulonglong2 v1 = *(const ulonglong2*)(p + 4);
                    nxt[q][0] = v0.x; nxt[q][1] = v0.y; nxt[q][2] = v1.x; nxt[q][3] = v1.y;
                }
            }

            // 5) arrive: tree (group atomic -> root -> gen bump). Release is
            //    detected per-warp at the top of the next step.
            __threadfence();
            __syncthreads();
            if (tid == 0) {
                unsigned a = atomicAdd((unsigned*)cg, 1u);
                if (a == 7u) {
                    *cg = 0u;
                    __threadfence();
                    unsigned r = atomicAdd((unsigned*)cr, 1u);
                    if (r == 7u) {
                        *cr = 0u;
                        __threadfence();
                        atomicAdd((unsigned*)gv, 1u);
                    }
                }
            }
        }
    }
}

// =============================================================================
// Epilogue kernels
// =============================================================================
__global__ void k_aspmean()
{
    int idx = blockIdx.x * 256 + threadIdx.x;   // d*64+n
    if (idx >= DF * NB) return;
    float s = 0.f;
    #pragma unroll
    for (int t = 0; t < LA; t++) s += g_afeat[(size_t)t * DF * NB + idx];
    g_aspv[idx] = s * (1.f / LA);
}

__global__ void k_dot()
{
    __shared__ float red[256];
    int t = blockIdx.x, tid = threadIdx.x;
    int n = tid & 63, part = tid >> 6;
    float s = 0.f;
    for (int d = part * 192; d < part * 192 + 192; d++)
        s += g_feat[((size_t)t * DF + d) * NB + n] * g_aspv[d * NB + n];
    red[tid] = s;
    __syncthreads();
    if (part == 0)
        g_dot[t * NB + n] = red[n] + red[64 + n] + red[128 + n] + red[192 + n];
}

__global__ void k_softmax(const int* __restrict__ text_len)
{
    __shared__ float red[256];
    int n = blockIdx.x, t = threadIdx.x;
    int len = text_len[n];
    float v = (t < len) ? g_dot[t * NB + n] : -1e30f;
    red[t] = v;
    __syncthreads();
    for (int o = 128; o > 0; o >>= 1) {
        if (t < o) red[t] = fmaxf(red[t], red[t + o]);
        __syncthreads();
    }
    float m = red[0];
    __syncthreads();
    float e = expf(v - m);
    red[t] = e;
    __syncthreads();
    for (int o = 128; o > 0; o >>= 1) {
        if (t < o) red[t] += red[t + o];
        __syncthreads();
    }
    g_att[t * NB + n] = e / red[0];
}

__global__ void k_pooled()
{
    int idx = blockIdx.x * 256 + threadIdx.x;   // d*64+n
    if (idx >= DF * NB) return;
    int n = idx & 63, d = idx >> 6;
    float s = 0.f;
    for (int t = 0; t < LSEQ; t++)
        s += g_feat[((size_t)t * DF + d) * NB + n] * g_att[t * NB + n];
    g_pooled[n * DF + d] = s * (1.f / 6.f);   // sum / NUM_HEADS
}

// C[n][o] = act(bias[o] + sum_k A[n][k] * W[o][k]);  A: 64x768, W: 768x768
__global__ __launch_bounds__(256) void k_mlp(
    const float* __restrict__ A, const float* __restrict__ W,
    const float* __restrict__ bias, float* __restrict__ C, int do_relu)
{
    __shared__ float As[64 * 68];   // [k][n]
    __shared__ float Ws[64 * 68];   // [k][o]
    int ob  = blockIdx.x * 64;
    int tid = threadIdx.x;
    int tx = tid & 15, ty = tid >> 4;
    int n0 = tx * 4, o0 = ty * 4;
    float acc[4][4];
    #pragma unroll
    for (int i = 0; i < 4; i++) {
        float b = bias[ob + o0 + i];
        #pragma unroll
        for (int j = 0; j < 4; j++) acc[i][j] = b;
    }
    for (int kb = 0; kb < DF; kb += 64) {
        __syncthreads();
        for (int f = tid; f < 64 * 64; f += 256) {
            int n = f >> 6, k = f & 63;
            As[k * 68 + n] = A[n * DF + kb + k];
        }
        for (int f = tid; f < 64 * 64; f += 256) {
            int o = f >> 6, k = f & 63;
            Ws[k * 68 + o] = W[(size_t)(ob + o) * DF + kb + k];
        }
        __syncthreads();
        #pragma unroll 4
        for (int k = 0; k < 64; k++) {
            float4 a = *(const float4*)&As[k * 68 + n0];
            float4 w = *(const float4*)&Ws[k * 68 + o0];
            float av[4] = {a.x, a.y, a.z, a.w};
            float wv[4] = {w.x, w.y, w.z, w.w};
            #pragma unroll
            for (int i = 0; i < 4; i++)
                #pragma unroll
                for (int j = 0; j < 4; j++)
                    acc[i][j] += wv[i] * av[j];
        }
    }
    #pragma unroll
    for (int i = 0; i < 4; i++)
        #pragma unroll
        for (int j = 0; j < 4; j++) {
            float v = acc[i][j];
            if (do_relu) v = fmaxf(v, 0.f);
            C[(n0 + j) * DF + ob + o0 + i] = v;
        }
}

__global__ void k_final(const float* __restrict__ Wf, const float* __restrict__ bf)
{
    int idx = blockIdx.x * 64 + threadIdx.x;
    if (idx >= NB * NCLS) return;
    int n = idx / NCLS, c = idx % NCLS;
    float s = bf[c];
    for (int k = 0; k < DF; k++) s += g_x2[n * DF + k] * Wf[c * DF + k];
    g_logit[n * NCLS + c] = s;
}

__global__ void k_out(float* __restrict__ out)
{
    size_t idx = (size_t)blockIdx.x * 256 + threadIdx.x;
    const size_t LOGN = (size_t)NB * LSEQ * NCLS;        // 49152
    const size_t TOT  = LOGN + (size_t)NB * LSEQ * DF;   // + 12582912
    if (idx >= TOT) return;
    if (idx < LOGN) {
        int c  = (int)(idx % NCLS);
        int nl = (int)(idx / NCLS);
        int n  = nl >> 8;
        out[idx] = g_logit[n * NCLS + c];
    } else {
        size_t r = idx - LOGN;
        int d  = (int)(r % DF);
        int nl = (int)(r / DF);
        int n  = nl >> 8;
        out[idx] = g_pooled[n * DF + d];
    }
}

// =============================================================================
extern "C" void kernel_launch(void* const* d_in, const int* in_sizes, int n_in,
                              void* d_out, int out_size)
{
    const int*   sentence = (const int*)d_in[0];
    const int*   aspect   = (const int*)d_in[1];
    const int*   text_len = (const int*)d_in[2];
    const float* emb      = (const float*)d_in[3];
    const float* w_ih_f   = (const float*)d_in[4];
    const float* w_hh_f   = (const float*)d_in[5];
    const float* b_ih_f   = (const float*)d_in[6];
    const float* b_hh_f   = (const float*)d_in[7];
    const float* w_ih_b   = (const float*)d_in[8];
    const float* w_hh_b   = (const float*)d_in[9];
    const float* b_ih_b   = (const float*)d_in[10];
    const float* b_hh_b   = (const float*)d_in[11];
    const float* W1       = (const float*)d_in[12];
    const float* b1       = (const float*)d_in[13];
    const float* W2       = (const float*)d_in[14];
    const float* b2       = (const float*)d_in[15];
    const float* Wf       = (const float*)d_in[16];
    const float* bf       = (const float*)d_in[17];
    float* out = (float*)d_out;

    float *xg_s, *xg_a, *feat, *afeat, *pooled, *x1, *x2;
    cudaGetSymbolAddress((void**)&xg_s,   g_xg_s);
    cudaGetSymbolAddress((void**)&xg_a,   g_xg_a);
    cudaGetSymbolAddress((void**)&feat,   g_feat);
    cudaGetSymbolAddress((void**)&afeat,  g_afeat);
    cudaGetSymbolAddress((void**)&pooled, g_pooled);
    cudaGetSymbolAddress((void**)&x1,     g_x1);
    cudaGetSymbolAddress((void**)&x2,     g_x2);

    cudaFuncSetAttribute(k_gemm_xg, cudaFuncAttributeMaxDynamicSharedMemorySize, SMEM_XG);
    cudaFuncSetAttribute(k_lstm,    cudaFuncAttributeMaxDynamicSharedMemorySize, SMEM_LSTM);

    k_gemm_xg<<<dim3(LSEQ + LA, 24), 256, SMEM_XG>>>(
        sentence, aspect, emb, w_ih_f, w_ih_b,
        b_ih_f, b_hh_f, b_ih_b, b_hh_b, xg_s, xg_a);

    // shift ncu's fixed capture window (-s 5 -c 1) onto k_lstm
    k_nop<<<1, 32>>>();
    k_nop<<<1, 32>>>();

    k_lstm<<<128, 256, SMEM_LSTM>>>(xg_s, feat, xg_a, afeat, w_hh_f, w_hh_b);

    k_aspmean<<<192, 256>>>();
    k_dot<<<LSEQ, 256>>>();
    k_softmax<<<NB, 256>>>(text_len);
    k_pooled<<<192, 256>>>();

    k_mlp<<<12, 256>>>(pooled, W1, b1, x1, 1);
    k_mlp<<<12, 256>>>(x1,     W2, b2, x2, 1);
    k_final<<<3, 64>>>(Wf, bf);

    size_t tot = (size_t)NB * LSEQ * NCLS + (size_t)NB * LSEQ * DF;
    k_out<<<(unsigned)((tot + 255) / 256), 256>>>(out);
}

// round 13
// speedup vs baseline: 1.3647x; 1.3647x over previous
#include <cuda_runtime.h>
#include <math.h>

#define NB     64
#define LSEQ   256
#define LA     8
#define EMBED  300
#define HID    384
#define D3     3072   // 2 * 4 * HID (both directions' gate columns)
#define DF     768    // 2 * HID
#define NCLS   3

// ---------------- scratch (device globals; allocation is forbidden) ----------
__device__ float g_xg_s[(size_t)LSEQ * D3 * NB];   // [t][col][n]
__device__ float g_xg_a[(size_t)LA   * D3 * NB];   // [t][col][n]
__device__ float g_feat [(size_t)LSEQ * DF * NB];  // [t][d][n]
__device__ float g_afeat[(size_t)LA   * DF * NB];  // [t][d][n]
__device__ float g_aspv[DF * NB];                  // [d][n]
__device__ float g_dot[LSEQ * NB];                 // [t][n]
__device__ float g_att[LSEQ * NB];                 // [t][n]
__device__ float g_pooled[NB * DF];                // [n][d]
__device__ float g_x1[NB * DF];
__device__ float g_x2[NB * DF];
__device__ float g_logit[NB * NCLS];
__device__ __align__(128) unsigned g_cnt2[64];     // [dir*32]
__device__ __align__(128) unsigned g_gen2[64];     // [dir*32]

// ---------------- f32x2 packed helpers (Blackwell FFMA2 / FADD2) -------------
typedef unsigned long long ull;

__device__ __forceinline__ ull pack2(float x, float y) {
    ull r; asm("mov.b64 %0, {%1,%2};" : "=l"(r) : "f"(x), "f"(y)); return r;
}
__device__ __forceinline__ ull fma2(ull a, ull b, ull c) {
    ull d; asm("fma.rn.f32x2 %0, %1, %2, %3;" : "=l"(d) : "l"(a), "l"(b), "l"(c));
    return d;
}
__device__ __forceinline__ ull add2(ull a, ull b) {
    ull d; asm("add.rn.f32x2 %0, %1, %2;" : "=l"(d) : "l"(a), "l"(b));
    return d;
}
__device__ __forceinline__ void unpack2(ull v, float& lo, float& hi) {
    asm("mov.b64 {%0,%1}, %2;" : "=f"(lo), "=f"(hi) : "l"(v));
}

__device__ __forceinline__ float sigm(float x) { return 1.f / (1.f + __expf(-x)); }
__device__ __forceinline__ float ftanh(float x) { return 2.f / (1.f + __expf(-2.f * x)) - 1.f; }

// cp.async 16B (L2 path, bypasses L1 -> coherent with other SMs' stcg writes)
__device__ __forceinline__ void cpa16(unsigned dst, const void* src) {
    asm volatile("cp.async.cg.shared.global [%0], [%1], 16;" :: "r"(dst), "l"(src));
}
__device__ __forceinline__ void cpa_commit() { asm volatile("cp.async.commit_group;"); }
__device__ __forceinline__ void cpa_wait0()  { asm volatile("cp.async.wait_group 0;"); }

// =============================================================================
// K1: fused embedding-gather + input-projection GEMM (both sequences)
// =============================================================================
#define SMEM_XG (60*132*8 + 60*68*4 + 256)

__global__ __launch_bounds__(256) void k_gemm_xg(
    const int* __restrict__ sent, const int* __restrict__ asp,
    const float* __restrict__ emb,
    const float* __restrict__ wf,  const float* __restrict__ wb,
    const float* __restrict__ bif, const float* __restrict__ bhf,
    const float* __restrict__ bib, const float* __restrict__ bhb,
    float* __restrict__ xg_s, float* __restrict__ xg_a)
{
    extern __shared__ char smc[];
    ull*   Bsu = (ull*)smc;                       // [e][c] dup pairs, stride 132
    float* As  = (float*)(smc + 60 * 132 * 8);    // [e][n] stride 68
    int*   tk  = (int*)(smc + 60 * 132 * 8 + 60 * 68 * 4);

    int t = blockIdx.x;
    const int* tok; int T; float* xg;
    if (t < LSEQ) { tok = sent; T = LSEQ; xg = xg_s; }
    else          { t -= LSEQ; tok = asp; T = LA; xg = xg_a; }

    const int cbase = blockIdx.y * 128;
    const int tid   = threadIdx.x;
    const int dir   = (cbase >= 1536) ? 1 : 0;
    const float* W  = dir ? wb  : wf;
    const float* bi = dir ? bib : bif;
    const float* bh = dir ? bhb : bhf;
    const int cl    = cbase - dir * 1536;

    if (tid < 64) tk[tid] = tok[tid * T + t];

    const int tx = tid & 15, ty = tid >> 4;
    const int n0 = tx * 4,   c0 = ty * 8;

    ull acc[8][2];
    #pragma unroll
    for (int i = 0; i < 8; i++) {
        float b = bi[cl + c0 + i] + bh[cl + c0 + i];
        acc[i][0] = pack2(b, b);
        acc[i][1] = acc[i][0];
    }

    for (int kb = 0; kb < 5; kb++) {
        const int e0 = kb * 60;
        __syncthreads();
        for (int f = tid; f < 64 * 60; f += 256) {
            int n = f / 60, e = f % 60;
            As[e * 68 + n] = emb[(size_t)tk[n] * EMBED + e0 + e];
        }
        for (int f = tid; f < 128 * 60; f += 256) {
            int c = f / 60, e = f % 60;
            float w = W[(size_t)(cl + c) * EMBED + e0 + e];
            Bsu[e * 132 + c] = pack2(w, w);
        }
        __syncthreads();
        #pragma unroll 4
        for (int e = 0; e < 60; e++) {
            ulonglong2 a2 = *(const ulonglong2*)&As[e * 68 + n0];
            ulonglong2 b0 = *(const ulonglong2*)&Bsu[e * 132 + c0];
            ulonglong2 b1 = *(const ulonglong2*)&Bsu[e * 132 + c0 + 2];
            ulonglong2 b2 = *(const ulonglong2*)&Bsu[e * 132 + c0 + 4];
            ulonglong2 b3 = *(const ulonglong2*)&Bsu[e * 132 + c0 + 6];
            acc[0][0] = fma2(b0.x, a2.x, acc[0][0]); acc[0][1] = fma2(b0.x, a2.y, acc[0][1]);
            acc[1][0] = fma2(b0.y, a2.x, acc[1][0]); acc[1][1] = fma2(b0.y, a2.y, acc[1][1]);
            acc[2][0] = fma2(b1.x, a2.x, acc[2][0]); acc[2][1] = fma2(b1.x, a2.y, acc[2][1]);
            acc[3][0] = fma2(b1.y, a2.x, acc[3][0]); acc[3][1] = fma2(b1.y, a2.y, acc[3][1]);
            acc[4][0] = fma2(b2.x, a2.x, acc[4][0]); acc[4][1] = fma2(b2.x, a2.y, acc[4][1]);
            acc[5][0] = fma2(b2.y, a2.x, acc[5][0]); acc[5][1] = fma2(b2.y, a2.y, acc[5][1]);
            acc[6][0] = fma2(b3.x, a2.x, acc[6][0]); acc[6][1] = fma2(b3.x, a2.y, acc[6][1]);
            acc[7][0] = fma2(b3.y, a2.x, acc[7][0]); acc[7][1] = fma2(b3.y, a2.y, acc[7][1]);
        }
    }

    size_t base = ((size_t)t * D3 + cbase + c0) * NB + n0;
    #pragma unroll
    for (int i = 0; i < 8; i++)
        *(ulonglong2*)&xg[base + (size_t)i * NB] = make_ulonglong2(acc[i][0], acc[i][1]);
}

// no-op launches: shift the ncu -s 5 -c 1 capture window onto k_lstm
__global__ void k_nop() {}

// =============================================================================
// K2: persistent BiLSTM (R9-proven best). 128 blocks (64 fwd + 64 bwd), 1/SM,
//   256 threads. K-split across warps: warp w owns k in [48w, 48w+48), stages
//   its own 12 KB h-chunk via warp-local cp.async. 6 rows x 8 n per thread;
//   partials reduced via f32x2; R4-proven single-level atomic+gen barrier.
// =============================================================================
#define GSW 1632   // per-warp gS slab: 24 rows * 68 floats
#define SMEM_LSTM (384*24*8 + 384*64*4 + 8*GSW*4 + 384*4)   // 225,792 B

__global__ __launch_bounds__(256) void k_lstm(
    const float* __restrict__ xg_s, float* __restrict__ feat_s,
    const float* __restrict__ xg_a, float* __restrict__ feat_a,
    const float* __restrict__ whf, const float* __restrict__ whb)
{
    extern __shared__ char smc[];
    ull*   wD = (ull*)smc;                               // [k][r] dup pairs, stride 24
    float* hS = (float*)(smc + 384 * 24 * 8);            // [k][n]
    float* gS = hS + 384 * 64;                           // [w][r][n] stride 68
    float* cS = gS + 8 * GSW;                            // [u][n] (u*64+n)

    const int b   = blockIdx.x;
    const int dir = b >> 6;
    const int ub  = (b & 63) * 6;
    const float* whh = dir ? whb : whf;
    const int tid = threadIdx.x;

    volatile unsigned* cnt = &g_cnt2[dir * 32];
    volatile unsigned* gen = &g_gen2[dir * 32];

    // persistent dup-weight load: 24 gate-rows x 384 k
    for (int idx = tid; idx < 24 * 384; idx += 256) {
        int k = idx / 24, r = idx % 24;
        int gt = r / 6, u = r % 6;
        float w = whh[(size_t)(gt * 384 + ub + u) * HID + k];
        wD[k * 24 + r] = pack2(w, w);
    }

    const int w    = tid >> 5;            // warp id = k-chunk
    const int lane = tid & 31;
    const int rg   = lane >> 3;           // row-group (gate): rows rg*6 .. rg*6+5
    const int nn   = (lane & 7) * 8;      // batch base: 8 n per thread
    const int kbase = w * 48;
    const unsigned hS_u = (unsigned)__cvta_generic_to_shared(hS);
    const unsigned hS_chunk = hS_u + (unsigned)kbase * 64u * 4u;   // w * 12288

    for (int phase = 0; phase < 2; phase++) {
        const int T = phase ? LA : LSEQ;
        const float* __restrict__ xg   = phase ? xg_a   : xg_s;
        float* __restrict__       feat = phase ? feat_a : feat_s;

        __syncthreads();
        for (int idx = tid; idx < 384; idx += 256) cS[idx] = 0.f;
        __syncthreads();

        // prefetch xg for step 0 (only warp 0 seeds xg into its partials)
        ull nxt[6][4];
        if (w == 0) {
            const int t0 = dir ? (T - 1) : 0;
            #pragma unroll
            for (int q = 0; q < 6; q++) {
                const float* p = &xg[((size_t)t0 * D3 + dir * 1536 + rg * 384 + ub + q) * NB + nn];
                ulonglong2 v0 = *(const ulonglong2*)p;
                ulonglong2 v1 = *(const ulonglong2*)(p + 4);
                nxt[q][0] = v0.x; nxt[q][1] = v0.y; nxt[q][2] = v1.x; nxt[q][3] = v1.y;
            }
        }

        for (int s = 0; s < T; s++) {
            const int t = dir ? (T - 1 - s) : s;

            // 1) warp-local staging of THIS warp's 48-k h chunk (12 KB)
            if (s > 0) {
                const int tp = dir ? (t + 1) : (t - 1);
                const float4* src =
                    (const float4*)&feat[((size_t)tp * DF + dir * HID + kbase) * NB];
                #pragma unroll
                for (int i = 0; i < 24; i++) {
                    int idx = lane + i * 32;
                    cpa16(hS_chunk + (unsigned)idx * 16u, src + idx);
                }
                cpa_commit();
            }

            ull acc[6][4];
            if (w == 0) {
                #pragma unroll
                for (int q = 0; q < 6; q++)
                    #pragma unroll
                    for (int j = 0; j < 4; j++) acc[q][j] = nxt[q][j];
            } else {
                #pragma unroll
                for (int q = 0; q < 6; q++)
                    #pragma unroll
                    for (int j = 0; j < 4; j++) acc[q][j] = 0ull;
            }

            // 2) gate GEMM on own chunk (producer == consumer == this warp)
            if (s > 0) {
                cpa_wait0();
                __syncwarp();
                #pragma unroll 4
                for (int kk = 0; kk < 48; kk++) {
                    const int k = kbase + kk;
                    ulonglong2 h0 = *(const ulonglong2*)&hS[k * 64 + nn];
                    ulonglong2 h1 = *(const ulonglong2*)&hS[k * 64 + nn + 4];
                    ulonglong2 wa = *(const ulonglong2*)&wD[k * 24 + rg * 6];
                    ulonglong2 wb2 = *(const ulonglong2*)&wD[k * 24 + rg * 6 + 2];
                    ulonglong2 wc2 = *(const ulonglong2*)&wD[k * 24 + rg * 6 + 4];
                    acc[0][0] = fma2(wa.x, h0.x, acc[0][0]);
                    acc[0][1] = fma2(wa.x, h0.y, acc[0][1]);
                    acc[0][2] = fma2(wa.x, h1.x, acc[0][2]);
                    acc[0][3] = fma2(wa.x, h1.y, acc[0][3]);
                    acc[1][0] = fma2(wa.y, h0.x, acc[1][0]);
                    acc[1][1] = fma2(wa.y, h0.y, acc[1][1]);
                    acc[1][2] = fma2(wa.y, h1.x, acc[1][2]);
                    acc[1][3] = fma2(wa.y, h1.y, acc[1][3]);
                    acc[2][0] = fma2(wb2.x, h0.x, acc[2][0]);
                    acc[2][1] = fma2(wb2.x, h0.y, acc[2][1]);
                    acc[2][2] = fma2(wb2.x, h1.x, acc[2][2]);
                    acc[2][3] = fma2(wb2.x, h1.y, acc[2][3]);
                    acc[3][0] = fma2(wb2.y, h0.x, acc[3][0]);
                    acc[3][1] = fma2(wb2.y, h0.y, acc[3][1]);
                    acc[3][2] = fma2(wb2.y, h1.x, acc[3][2]);
                    acc[3][3] = fma2(wb2.y, h1.y, acc[3][3]);
                    acc[4][0] = fma2(wc2.x, h0.x, acc[4][0]);
                    acc[4][1] = fma2(wc2.x, h0.y, acc[4][1]);
                    acc[4][2] = fma2(wc2.x, h1.x, acc[4][2]);
                    acc[4][3] = fma2(wc2.x, h1.y, acc[4][3]);
                    acc[5][0] = fma2(wc2.y, h0.x, acc[5][0]);
                    acc[5][1] = fma2(wc2.y, h0.y, acc[5][1]);
                    acc[5][2] = fma2(wc2.y, h1.x, acc[5][2]);
                    acc[5][3] = fma2(wc2.y, h1.y, acc[5][3]);
                }
            }

            // partials -> this warp's gS slab
            #pragma unroll
            for (int q = 0; q < 6; q++) {
                float* gr = &gS[w * GSW + (rg * 6 + q) * 68 + nn];
                *(ulonglong2*)gr       = make_ulonglong2(acc[q][0], acc[q][1]);
                *(ulonglong2*)(gr + 4) = make_ulonglong2(acc[q][2], acc[q][3]);
            }
            __syncthreads();

            // 3) reduce 8 warp-partials (f32x2), activations, h write.
            if (tid < 192) {
                int u = tid >> 5, n0 = (tid & 31) * 2;
                ull vi = 0, vf = 0, vg = 0, vo = 0;
                #pragma unroll
                for (int ww = 0; ww < 8; ww++) {
                    const float* gw = gS + ww * GSW;
                    vi = add2(vi, *(const ull*)&gw[(0 * 6 + u) * 68 + n0]);
                    vf = add2(vf, *(const ull*)&gw[(1 * 6 + u) * 68 + n0]);
                    vg = add2(vg, *(const ull*)&gw[(2 * 6 + u) * 68 + n0]);
                    vo = add2(vo, *(const ull*)&gw[(3 * 6 + u) * 68 + n0]);
                }
                float gi0, gi1, gf0, gf1, gg0, gg1, go0, go1;
                unpack2(vi, gi0, gi1); unpack2(vf, gf0, gf1);
                unpack2(vg, gg0, gg1); unpack2(vo, go0, go1);
                float c0 = sigm(gf0) * cS[u * 64 + n0]     + sigm(gi0) * ftanh(gg0);
                float c1 = sigm(gf1) * cS[u * 64 + n0 + 1] + sigm(gi1) * ftanh(gg1);
                cS[u * 64 + n0]     = c0;
                cS[u * 64 + n0 + 1] = c1;
                ull hv = pack2(sigm(go0) * ftanh(c0), sigm(go1) * ftanh(c1));
                __stcg((ull*)&feat[((size_t)t * DF + dir * HID + ub + u) * NB + n0], hv);
            }

            // 4) prefetch xg for next step (warp 0; hides LDG under barrier)
            if (w == 0 && s + 1 < T) {
                const int tn = dir ? (T - 2 - s) : (s + 1);
                #pragma unroll
                for (int q = 0; q < 6; q++) {
                    const float* p = &xg[((size_t)tn * D3 + dir * 1536 + rg * 384 + ub + q) * NB + nn];
                    ulonglong2 v0 = *(const ulonglong2*)p;
                    ulonglong2 v1 = *(const ulonglong2*)(p + 4);
                    nxt[q][0] = v0.x; nxt[q][1] = v0.y; nxt[q][2] = v1.x; nxt[q][3] = v1.y;
                }
            }

            // 5) per-direction grid barrier (R4-proven: fence + bar + atomic)
            __threadfence();
            __syncthreads();
            if (tid == 0) {
                unsigned g = *gen;
                unsigned a = atomicAdd((unsigned*)cnt, 1u);
                if (a == 63u) {
                    *cnt = 0u;
                    __threadfence();
                    atomicAdd((unsigned*)gen, 1u);
                } else {
                    while (*gen == g) { }
                }
                __threadfence();
            }
            __syncthreads();
        }
    }
}

// =============================================================================
// Epilogue kernels
// =============================================================================
__global__ void k_aspmean()
{
    int idx = blockIdx.x * 256 + threadIdx.x;   // d*64+n
    if (idx >= DF * NB) return;
    float s = 0.f;
    #pragma unroll
    for (int t = 0; t < LA; t++) s += g_afeat[(size_t)t * DF * NB + idx];
    g_aspv[idx] = s * (1.f / LA);
}

__global__ void k_dot()
{
    __shared__ float red[256];
    int t = blockIdx.x, tid = threadIdx.x;
    int n = tid & 63, part = tid >> 6;
    float s = 0.f;
    for (int d = part * 192; d < part * 192 + 192; d++)
        s += g_feat[((size_t)t * DF + d) * NB + n] * g_aspv[d * NB + n];
    red[tid] = s;
    __syncthreads();
    if (part == 0)
        g_dot[t * NB + n] = red[n] + red[64 + n] + red[128 + n] + red[192 + n];
}

__global__ void k_softmax(const int* __restrict__ text_len)
{
    __shared__ float red[256];
    int n = blockIdx.x, t = threadIdx.x;
    int len = text_len[n];
    float v = (t < len) ? g_dot[t * NB + n] : -1e30f;
    red[t] = v;
    __syncthreads();
    for (int o = 128; o > 0; o >>= 1) {
        if (t < o) red[t] = fmaxf(red[t], red[t + o]);
        __syncthreads();
    }
    float m = red[0];
    __syncthreads();
    float e = expf(v - m);
    red[t] = e;
    __syncthreads();
    for (int o = 128; o > 0; o >>= 1) {
        if (t < o) red[t] += red[t + o];
        __syncthreads();
    }
    g_att[t * NB + n] = e / red[0];
}

__global__ void k_pooled()
{
    int idx = blockIdx.x * 256 + threadIdx.x;   // d*64+n
    if (idx >= DF * NB) return;
    int n = idx & 63, d = idx >> 6;
    float s = 0.f;
    for (int t = 0; t < LSEQ; t++)
        s += g_feat[((size_t)t * DF + d) * NB + n] * g_att[t * NB + n];
    g_pooled[n * DF + d] = s * (1.f / 6.f);   // sum / NUM_HEADS
}

// C[n][o] = act(bias[o] + sum_k A[n][k] * W[o][k]);  A: 64x768, W: 768x768
__global__ __launch_bounds__(256) void k_mlp(
    const float* __restrict__ A, const float* __restrict__ W,
    const float* __restrict__ bias, float* __restrict__ C, int do_relu)
{
    __shared__ float As[64 * 68];   // [k][n]
    __shared__ float Ws[64 * 68];   // [k][o]
    int ob  = blockIdx.x * 64;
    int tid = threadIdx.x;
    int tx = tid & 15, ty = tid >> 4;
    int n0 = tx * 4, o0 = ty * 4;
    float acc[4][4];
    #pragma unroll
    for (int i = 0; i < 4; i++) {
        float b = bias[ob + o0 + i];
        #pragma unroll
        for (int j = 0; j < 4; j++) acc[i][j] = b;
    }
    for (int kb = 0; kb < DF; kb += 64) {
        __syncthreads();
        for (int f = tid; f < 64 * 64; f += 256) {
            int n = f >> 6, k = f & 63;
            As[k * 68 + n] = A[n * DF + kb + k];
        }
        for (int f = tid; f < 64 * 64; f += 256) {
            int o = f >> 6, k = f & 63;
            Ws[k * 68 + o] = W[(size_t)(ob + o) * DF + kb + k];
        }
        __syncthreads();
        #pragma unroll 4
        for (int k = 0; k < 64; k++) {
            float4 a = *(const float4*)&As[k * 68 + n0];
            float4 w = *(const float4*)&Ws[k * 68 + o0];
            float av[4] = {a.x, a.y, a.z, a.w};
            float wv[4] = {w.x, w.y, w.z, w.w};
            #pragma unroll
            for (int i = 0; i < 4; i++)
                #pragma unroll
                for (int j = 0; j < 4; j++)
                    acc[i][j] += wv[i] * av[j];
        }
    }
    #pragma unroll
    for (int i = 0; i < 4; i++)
        #pragma unroll
        for (int j = 0; j < 4; j++) {
            float v = acc[i][j];
            if (do_relu) v = fmaxf(v, 0.f);
            C[(n0 + j) * DF + ob + o0 + i] = v;
        }
}

__global__ void k_final(const float* __restrict__ Wf, const float* __restrict__ bf)
{
    int idx = blockIdx.x * 64 + threadIdx.x;
    if (idx >= NB * NCLS) return;
    int n = idx / NCLS, c = idx % NCLS;
    float s = bf[c];
    for (int k = 0; k < DF; k++) s += g_x2[n * DF + k] * Wf[c * DF + k];
    g_logit[n * NCLS + c] = s;
}

__global__ void k_out(float* __restrict__ out)
{
    size_t idx = (size_t)blockIdx.x * 256 + threadIdx.x;
    const size_t LOGN = (size_t)NB * LSEQ * NCLS;        // 49152
    const size_t TOT  = LOGN + (size_t)NB * LSEQ * DF;   // + 12582912
    if (idx >= TOT) return;
    if (idx < LOGN) {
        int c  = (int)(idx % NCLS);
        int nl = (int)(idx / NCLS);
        int n  = nl >> 8;
        out[idx] = g_logit[n * NCLS + c];
    } else {
        size_t r = idx - LOGN;
        int d  = (int)(r % DF);
        int nl = (int)(r / DF);
        int n  = nl >> 8;
        out[idx] = g_pooled[n * DF + d];
    }
}

// =============================================================================
extern "C" void kernel_launch(void* const* d_in, const int* in_sizes, int n_in,
                              void* d_out, int out_size)
{
    const int*   sentence = (const int*)d_in[0];
    const int*   aspect   = (const int*)d_in[1];
    const int*   text_len = (const int*)d_in[2];
    const float* emb      = (const float*)d_in[3];
    const float* w_ih_f   = (const float*)d_in[4];
    const float* w_hh_f   = (const float*)d_in[5];
    const float* b_ih_f   = (const float*)d_in[6];
    const float* b_hh_f   = (const float*)d_in[7];
    const float* w_ih_b   = (const float*)d_in[8];
    const float* w_hh_b   = (const float*)d_in[9];
    const float* b_ih_b   = (const float*)d_in[10];
    const float* b_hh_b   = (const float*)d_in[11];
    const float* W1       = (const float*)d_in[12];
    const float* b1       = (const float*)d_in[13];
    const float* W2       = (const float*)d_in[14];
    const float* b2       = (const float*)d_in[15];
    const float* Wf       = (const float*)d_in[16];
    const float* bf       = (const float*)d_in[17];
    float* out = (float*)d_out;

    float *xg_s, *xg_a, *feat, *afeat, *pooled, *x1, *x2;
    cudaGetSymbolAddress((void**)&xg_s,   g_xg_s);
    cudaGetSymbolAddress((void**)&xg_a,   g_xg_a);
    cudaGetSymbolAddress((void**)&feat,   g_feat);
    cudaGetSymbolAddress((void**)&afeat,  g_afeat);
    cudaGetSymbolAddress((void**)&pooled, g_pooled);
    cudaGetSymbolAddress((void**)&x1,     g_x1);
    cudaGetSymbolAddress((void**)&x2,     g_x2);

    cudaFuncSetAttribute(k_gemm_xg, cudaFuncAttributeMaxDynamicSharedMemorySize, SMEM_XG);
    cudaFuncSetAttribute(k_lstm,    cudaFuncAttributeMaxDynamicSharedMemorySize, SMEM_LSTM);

    k_gemm_xg<<<dim3(LSEQ + LA, 24), 256, SMEM_XG>>>(
        sentence, aspect, emb, w_ih_f, w_ih_b,
        b_ih_f, b_hh_f, b_ih_b, b_hh_b, xg_s, xg_a);

    // shift ncu's fixed capture window (-s 5 -c 1) onto k_lstm
    k_nop<<<1, 32>>>();
    k_nop<<<1, 32>>>();

    k_lstm<<<128, 256, SMEM_LSTM>>>(xg_s, feat, xg_a, afeat, w_hh_f, w_hh_b);

    k_aspmean<<<192, 256>>>();
    k_dot<<<LSEQ, 256>>>();
    k_softmax<<<NB, 256>>>(text_len);
    k_pooled<<<192, 256>>>();

    k_mlp<<<12, 256>>>(pooled, W1, b1, x1, 1);
    k_mlp<<<12, 256>>>(x1,     W2, b2, x2, 1);
    k_final<<<3, 64>>>(Wf, bf);

    size_t tot = (size_t)NB * LSEQ * NCLS + (size_t)NB * LSEQ * DF;
    k_out<<<(unsigned)((tot + 255) / 256), 256>>>(out);
}

// round 14
// speedup vs baseline: 1.5294x; 1.1207x over previous
#include <cuda_runtime.h>
#include <math.h>

#define NB     64
#define LSEQ   256
#define LA     8
#define EMBED  300
#define HID    384
#define D3     3072   // 2 * 4 * HID (both directions' gate columns)
#define DF     768    // 2 * HID
#define NCLS   3

// ---------------- scratch (device globals; allocation is forbidden) ----------
__device__ float g_xg_s[(size_t)LSEQ * D3 * NB];   // [t][col][n]
__device__ float g_xg_a[(size_t)LA   * D3 * NB];   // [t][col][n]
__device__ float g_feat [(size_t)LSEQ * DF * NB];  // [t][d][n]
__device__ float g_afeat[(size_t)LA   * DF * NB];  // [t][d][n]
__device__ float g_aspv[DF * NB];                  // [d][n]
__device__ float g_dot[LSEQ * NB];                 // [t][n]
__device__ float g_att[LSEQ * NB];                 // [t][n]
__device__ float g_pooled[NB * DF];                // [n][d]
__device__ float g_x1[NB * DF];
__device__ float g_x2[NB * DF];
__device__ float g_logit[NB * NCLS];
// 4 independent barriers: (dir, batch-group), each on its own 128B lines
__device__ __align__(128) unsigned g_cnt2[4 * 32];
__device__ __align__(128) unsigned g_gen2[4 * 32];

// ---------------- f32x2 packed helpers (Blackwell FFMA2 / FADD2) -------------
typedef unsigned long long ull;

__device__ __forceinline__ ull pack2(float x, float y) {
    ull r; asm("mov.b64 %0, {%1,%2};" : "=l"(r) : "f"(x), "f"(y)); return r;
}
__device__ __forceinline__ ull fma2(ull a, ull b, ull c) {
    ull d; asm("fma.rn.f32x2 %0, %1, %2, %3;" : "=l"(d) : "l"(a), "l"(b), "l"(c));
    return d;
}
__device__ __forceinline__ ull add2(ull a, ull b) {
    ull d; asm("add.rn.f32x2 %0, %1, %2;" : "=l"(d) : "l"(a), "l"(b));
    return d;
}
__device__ __forceinline__ void unpack2(ull v, float& lo, float& hi) {
    asm("mov.b64 {%0,%1}, %2;" : "=f"(lo), "=f"(hi) : "l"(v));
}

__device__ __forceinline__ float sigm(float x) { return 1.f / (1.f + __expf(-x)); }
__device__ __forceinline__ float ftanh(float x) { return 2.f / (1.f + __expf(-2.f * x)) - 1.f; }

// cp.async 16B (L2 path, bypasses L1 -> coherent with other SMs' stcg writes)
__device__ __forceinline__ void cpa16(unsigned dst, const void* src) {
    asm volatile("cp.async.cg.shared.global [%0], [%1], 16;" :: "r"(dst), "l"(src));
}
__device__ __forceinline__ void cpa_commit() { asm volatile("cp.async.commit_group;"); }
__device__ __forceinline__ void cpa_wait0()  { asm volatile("cp.async.wait_group 0;"); }

// =============================================================================
// K1: fused embedding-gather + input-projection GEMM (both sequences)
// =============================================================================
#define SMEM_XG (60*132*8 + 60*68*4 + 256)

__global__ __launch_bounds__(256) void k_gemm_xg(
    const int* __restrict__ sent, const int* __restrict__ asp,
    const float* __restrict__ emb,
    const float* __restrict__ wf,  const float* __restrict__ wb,
    const float* __restrict__ bif, const float* __restrict__ bhf,
    const float* __restrict__ bib, const float* __restrict__ bhb,
    float* __restrict__ xg_s, float* __restrict__ xg_a)
{
    extern __shared__ char smc[];
    ull*   Bsu = (ull*)smc;                       // [e][c] dup pairs, stride 132
    float* As  = (float*)(smc + 60 * 132 * 8);    // [e][n] stride 68
    int*   tk  = (int*)(smc + 60 * 132 * 8 + 60 * 68 * 4);

    int t = blockIdx.x;
    const int* tok; int T; float* xg;
    if (t < LSEQ) { tok = sent; T = LSEQ; xg = xg_s; }
    else          { t -= LSEQ; tok = asp; T = LA; xg = xg_a; }

    const int cbase = blockIdx.y * 128;
    const int tid   = threadIdx.x;
    const int dir   = (cbase >= 1536) ? 1 : 0;
    const float* W  = dir ? wb  : wf;
    const float* bi = dir ? bib : bif;
    const float* bh = dir ? bhb : bhf;
    const int cl    = cbase - dir * 1536;

    if (tid < 64) tk[tid] = tok[tid * T + t];

    const int tx = tid & 15, ty = tid >> 4;
    const int n0 = tx * 4,   c0 = ty * 8;

    ull acc[8][2];
    #pragma unroll
    for (int i = 0; i < 8; i++) {
        float b = bi[cl + c0 + i] + bh[cl + c0 + i];
        acc[i][0] = pack2(b, b);
        acc[i][1] = acc[i][0];
    }

    for (int kb = 0; kb < 5; kb++) {
        const int e0 = kb * 60;
        __syncthreads();
        for (int f = tid; f < 64 * 60; f += 256) {
            int n = f / 60, e = f % 60;
            As[e * 68 + n] = emb[(size_t)tk[n] * EMBED + e0 + e];
        }
        for (int f = tid; f < 128 * 60; f += 256) {
            int c = f / 60, e = f % 60;
            float w = W[(size_t)(cl + c) * EMBED + e0 + e];
            Bsu[e * 132 + c] = pack2(w, w);
        }
        __syncthreads();
        #pragma unroll 4
        for (int e = 0; e < 60; e++) {
            ulonglong2 a2 = *(const ulonglong2*)&As[e * 68 + n0];
            ulonglong2 b0 = *(const ulonglong2*)&Bsu[e * 132 + c0];
            ulonglong2 b1 = *(const ulonglong2*)&Bsu[e * 132 + c0 + 2];
            ulonglong2 b2 = *(const ulonglong2*)&Bsu[e * 132 + c0 + 4];
            ulonglong2 b3 = *(const ulonglong2*)&Bsu[e * 132 + c0 + 6];
            acc[0][0] = fma2(b0.x, a2.x, acc[0][0]); acc[0][1] = fma2(b0.x, a2.y, acc[0][1]);
            acc[1][0] = fma2(b0.y, a2.x, acc[1][0]); acc[1][1] = fma2(b0.y, a2.y, acc[1][1]);
            acc[2][0] = fma2(b1.x, a2.x, acc[2][0]); acc[2][1] = fma2(b1.x, a2.y, acc[2][1]);
            acc[3][0] = fma2(b1.y, a2.x, acc[3][0]); acc[3][1] = fma2(b1.y, a2.y, acc[3][1]);
            acc[4][0] = fma2(b2.x, a2.x, acc[4][0]); acc[4][1] = fma2(b2.x, a2.y, acc[4][1]);
            acc[5][0] = fma2(b2.y, a2.x, acc[5][0]); acc[5][1] = fma2(b2.y, a2.y, acc[5][1]);
            acc[6][0] = fma2(b3.x, a2.x, acc[6][0]); acc[6][1] = fma2(b3.x, a2.y, acc[6][1]);
            acc[7][0] = fma2(b3.y, a2.x, acc[7][0]); acc[7][1] = fma2(b3.y, a2.y, acc[7][1]);
        }
    }

    size_t base = ((size_t)t * D3 + cbase + c0) * NB + n0;
    #pragma unroll
    for (int i = 0; i < 8; i++)
        *(ulonglong2*)&xg[base + (size_t)i * NB] = make_ulonglong2(acc[i][0], acc[i][1]);
}

// no-op launches: shift the ncu -s 5 -c 1 capture window onto k_lstm
__global__ void k_nop() {}

// =============================================================================
// K2: persistent BiLSTM with BATCH-SPLIT barriers.
//   128 blocks = 2 dirs x 2 batch-groups x 32 hidden-split blocks.
//   Block owns 12 hidden units (48 gate rows) x 32 batch. Barrier spans only
//   32 blocks -> halves arrival serialization, straggler spread, staging bytes.
//   K-split across 8 warps (48 k each, warp-local cp.async staging of a 6 KB
//   chunk). Per-thread micro-tile: 6 rows x 8 batch (24 f32x2 accumulators).
// =============================================================================
#define GSW2 (48*36)   // per-warp gS slab: 48 rows * 36 floats (16B-aligned rows)
#define SMEM_LSTM ((384*64 + 384*32 + 8*GSW2 + 12*32) * 4)   // 204,288 B

__global__ __launch_bounds__(256) void k_lstm(
    const float* __restrict__ xg_s, float* __restrict__ feat_s,
    const float* __restrict__ xg_a, float* __restrict__ feat_a,
    const float* __restrict__ whf, const float* __restrict__ whb)
{
    extern __shared__ float smf[];
    float* wS = smf;                    // [k][64]: slot k*64 + rg*8 + q (q<6)
    float* hS = smf + 384 * 64;         // [k][32]
    float* gS = hS + 384 * 32;          // [slab][r][36]
    float* cS = gS + 8 * GSW2;          // [u][32]

    const int b     = blockIdx.x;
    const int dir   = b >> 6;
    const int bb    = b & 63;
    const int grp   = bb >> 5;          // batch group (n in [grp*32, grp*32+32))
    const int blk   = bb & 31;
    const int ub    = blk * 12;         // first owned hidden unit
    const int nbase = grp * 32;
    const float* whh = dir ? whb : whf;
    const int tid = threadIdx.x;

    volatile unsigned* cnt = &g_cnt2[(dir * 2 + grp) * 32];
    volatile unsigned* gen = &g_gen2[(dir * 2 + grp) * 32];

    // persistent weight load: 48 gate-rows x 384 k (non-duplicated)
    for (int idx = tid; idx < 48 * 384; idx += 256) {
        int k = idx / 48, r = idx % 48;
        int gt = r / 12, u = r % 12;
        wS[k * 64 + (r / 6) * 8 + (r % 6)] =
            whh[(size_t)(gt * 384 + ub + u) * HID + k];
    }

    const int w    = tid >> 5;          // warp id = k-chunk
    const int lane = tid & 31;
    const int rg   = lane >> 2;         // 8 row-groups of 6 rows
    const int nn   = (lane & 3) * 8;    // 4 n-groups of 8 (local batch)
    const int kbase = w * 48;
    const unsigned hS_u = (unsigned)__cvta_generic_to_shared(hS);

    for (int phase = 0; phase < 2; phase++) {
        const int T = phase ? LA : LSEQ;
        const float* __restrict__ xg   = phase ? xg_a   : xg_s;
        float* __restrict__       feat = phase ? feat_a : feat_s;

        __syncthreads();
        for (int idx = tid; idx < 12 * 32; idx += 256) cS[idx] = 0.f;
        __syncthreads();

        // prefetch xg for step 0 (only warp 0 seeds xg into its partials)
        ull nxt[6][4];
        if (w == 0) {
            const int t0 = dir ? (T - 1) : 0;
            #pragma unroll
            for (int q = 0; q < 6; q++) {
                int r = rg * 6 + q;
                int col = dir * 1536 + (r / 12) * 384 + ub + (r % 12);
                const float* p = &xg[((size_t)t0 * D3 + col) * NB + nbase + nn];
                ulonglong2 v0 = *(const ulonglong2*)p;
                ulonglong2 v1 = *(const ulonglong2*)(p + 4);
                nxt[q][0] = v0.x; nxt[q][1] = v0.y; nxt[q][2] = v1.x; nxt[q][3] = v1.y;
            }
        }

        for (int s = 0; s < T; s++) {
            const int t = dir ? (T - 1 - s) : s;

            // 1) warp-local staging of this warp's 48-k x 32-n h chunk (6 KB)
            if (s > 0) {
                const int tp = dir ? (t + 1) : (t - 1);
                const char* srcb = (const char*)
                    &feat[((size_t)tp * DF + dir * HID + kbase) * NB + nbase];
                #pragma unroll
                for (int i = 0; i < 12; i++) {
                    int c = lane + i * 32;           // 0..383
                    int row = c >> 3, off = c & 7;   // 48 rows x 8 chunks
                    cpa16(hS_u + (unsigned)(kbase + row) * 128u + (unsigned)off * 16u,
                          srcb + (size_t)row * 256 + off * 16);
                }
                cpa_commit();
            }

            ull acc[6][4];
            if (w == 0) {
                #pragma unroll
                for (int q = 0; q < 6; q++)
                    #pragma unroll
                    for (int j = 0; j < 4; j++) acc[q][j] = nxt[q][j];
            } else {
                #pragma unroll
                for (int q = 0; q < 6; q++)
                    #pragma unroll
                    for (int j = 0; j < 4; j++) acc[q][j] = 0ull;
            }

            // 2) gate GEMM on own chunk (producer == consumer == this warp)
            if (s > 0) {
                cpa_wait0();
                __syncwarp();
                #pragma unroll 4
                for (int kk = 0; kk < 48; kk++) {
                    const int k = kbase + kk;
                    ulonglong2 ha = *(const ulonglong2*)&hS[k * 32 + nn];
                    ulonglong2 hb = *(const ulonglong2*)&hS[k * 32 + nn + 4];
                    float4 w4 = *(const float4*)&wS[k * 64 + rg * 8];
                    float2 w2 = *(const float2*)&wS[k * 64 + rg * 8 + 4];
                    ull wd0 = pack2(w4.x, w4.x);
                    ull wd1 = pack2(w4.y, w4.y);
                    ull wd2 = pack2(w4.z, w4.z);
                    ull wd3 = pack2(w4.w, w4.w);
                    ull wd4 = pack2(w2.x, w2.x);
                    ull wd5 = pack2(w2.y, w2.y);
                    acc[0][0] = fma2(wd0, ha.x, acc[0][0]);
                    acc[0][1] = fma2(wd0, ha.y, acc[0][1]);
                    acc[0][2] = fma2(wd0, hb.x, acc[0][2]);
                    acc[0][3] = fma2(wd0, hb.y, acc[0][3]);
                    acc[1][0] = fma2(wd1, ha.x, acc[1][0]);
                    acc[1][1] = fma2(wd1, ha.y, acc[1][1]);
                    acc[1][2] = fma2(wd1, hb.x, acc[1][2]);
                    acc[1][3] = fma2(wd1, hb.y, acc[1][3]);
                    acc[2][0] = fma2(wd2, ha.x, acc[2][0]);
                    acc[2][1] = fma2(wd2, ha.y, acc[2][1]);
                    acc[2][2] = fma2(wd2, hb.x, acc[2][2]);
                    acc[2][3] = fma2(wd2, hb.y, acc[2][3]);
                    acc[3][0] = fma2(wd3, ha.x, acc[3][0]);
                    acc[3][1] = fma2(wd3, ha.y, acc[3][1]);
                    acc[3][2] = fma2(wd3, hb.x, acc[3][2]);
                    acc[3][3] = fma2(wd3, hb.y, acc[3][3]);
                    acc[4][0] = fma2(wd4, ha.x, acc[4][0]);
                    acc[4][1] = fma2(wd4, ha.y, acc[4][1]);
                    acc[4][2] = fma2(wd4, hb.x, acc[4][2]);
                    acc[4][3] = fma2(wd4, hb.y, acc[4][3]);
                    acc[5][0] = fma2(wd5, ha.x, acc[5][0]);
                    acc[5][1] = fma2(wd5, ha.y, acc[5][1]);
                    acc[5][2] = fma2(wd5, hb.x, acc[5][2]);
                    acc[5][3] = fma2(wd5, hb.y, acc[5][3]);
                }
            }

            // partials -> this warp's gS slab
            #pragma unroll
            for (int q = 0; q < 6; q++) {
                int r = rg * 6 + q;
                float* gr = &gS[w * GSW2 + r * 36 + nn];
                *(ulonglong2*)gr       = make_ulonglong2(acc[q][0], acc[q][1]);
                *(ulonglong2*)(gr + 4) = make_ulonglong2(acc[q][2], acc[q][3]);
            }
            __syncthreads();

            // 3) reduce 8 warp-partials (f32x2), activations, h write.
            //    192 threads x 2 n = 12 units x 32 n outputs.
            if (tid < 192) {
                int u = tid >> 4, n0 = (tid & 15) * 2;
                ull vi = 0, vf = 0, vg = 0, vo = 0;
                #pragma unroll
                for (int ww = 0; ww < 8; ww++) {
                    const float* gw = gS + ww * GSW2;
                    vi = add2(vi, *(const ull*)&gw[(0 * 12 + u) * 36 + n0]);
                    vf = add2(vf, *(const ull*)&gw[(1 * 12 + u) * 36 + n0]);
                    vg = add2(vg, *(const ull*)&gw[(2 * 12 + u) * 36 + n0]);
                    vo = add2(vo, *(const ull*)&gw[(3 * 12 + u) * 36 + n0]);
                }
                float gi0, gi1, gf0, gf1, gg0, gg1, go0, go1;
                unpack2(vi, gi0, gi1); unpack2(vf, gf0, gf1);
                unpack2(vg, gg0, gg1); unpack2(vo, go0, go1);
                float c0 = sigm(gf0) * cS[u * 32 + n0]     + sigm(gi0) * ftanh(gg0);
                float c1 = sigm(gf1) * cS[u * 32 + n0 + 1] + sigm(gi1) * ftanh(gg1);
                cS[u * 32 + n0]     = c0;
                cS[u * 32 + n0 + 1] = c1;
                ull hv = pack2(sigm(go0) * ftanh(c0), sigm(go1) * ftanh(c1));
                __stcg((ull*)&feat[((size_t)t * DF + dir * HID + ub + u) * NB + nbase + n0], hv);
            }

            // 4) prefetch xg for next step (warp 0; hides LDG under barrier)
            if (w == 0 && s + 1 < T) {
                const int tn = dir ? (T - 2 - s) : (s + 1);
                #pragma unroll
                for (int q = 0; q < 6; q++) {
                    int r = rg * 6 + q;
                    int col = dir * 1536 + (r / 12) * 384 + ub + (r % 12);
                    const float* p = &xg[((size_t)tn * D3 + col) * NB + nbase + nn];
                    ulonglong2 v0 = *(const ulonglong2*)p;
                    ulonglong2 v1 = *(const ulonglong2*)(p + 4);
                    nxt[q][0] = v0.x; nxt[q][1] = v0.y; nxt[q][2] = v1.x; nxt[q][3] = v1.y;
                }
            }

            // 5) per-(dir,group) grid barrier over 32 blocks (R4-proven form)
            __threadfence();
            __syncthreads();
            if (tid == 0) {
                unsigned g = *gen;
                unsigned a = atomicAdd((unsigned*)cnt, 1u);
                if (a == 31u) {
                    *cnt = 0u;
                    __threadfence();
                    atomicAdd((unsigned*)gen, 1u);
                } else {
                    while (*gen == g) { }
                }
                __threadfence();
            }
            __syncthreads();
        }
    }
}

// =============================================================================
// Epilogue kernels
// =============================================================================
__global__ void k_aspmean()
{
    int idx = blockIdx.x * 256 + threadIdx.x;   // d*64+n
    if (idx >= DF * NB) return;
    float s = 0.f;
    #pragma unroll
    for (int t = 0; t < LA; t++) s += g_afeat[(size_t)t * DF * NB + idx];
    g_aspv[idx] = s * (1.f / LA);
}

__global__ void k_dot()
{
    __shared__ float red[256];
    int t = blockIdx.x, tid = threadIdx.x;
    int n = tid & 63, part = tid >> 6;
    float s = 0.f;
    for (int d = part * 192; d < part * 192 + 192; d++)
        s += g_feat[((size_t)t * DF + d) * NB + n] * g_aspv[d * NB + n];
    red[tid] = s;
    __syncthreads();
    if (part == 0)
        g_dot[t * NB + n] = red[n] + red[64 + n] + red[128 + n] + red[192 + n];
}

__global__ void k_softmax(const int* __restrict__ text_len)
{
    __shared__ float red[256];
    int n = blockIdx.x, t = threadIdx.x;
    int len = text_len[n];
    float v = (t < len) ? g_dot[t * NB + n] : -1e30f;
    red[t] = v;
    __syncthreads();
    for (int o = 128; o > 0; o >>= 1) {
        if (t < o) red[t] = fmaxf(red[t], red[t + o]);
        __syncthreads();
    }
    float m = red[0];
    __syncthreads();
    float e = expf(v - m);
    red[t] = e;
    __syncthreads();
    for (int o = 128; o > 0; o >>= 1) {
        if (t < o) red[t] += red[t + o];
        __syncthreads();
    }
    g_att[t * NB + n] = e / red[0];
}

__global__ void k_pooled()
{
    int idx = blockIdx.x * 256 + threadIdx.x;   // d*64+n
    if (idx >= DF * NB) return;
    int n = idx & 63, d = idx >> 6;
    float s = 0.f;
    for (int t = 0; t < LSEQ; t++)
        s += g_feat[((size_t)t * DF + d) * NB + n] * g_att[t * NB + n];
    g_pooled[n * DF + d] = s * (1.f / 6.f);   // sum / NUM_HEADS
}

// C[n][o] = act(bias[o] + sum_k A[n][k] * W[o][k]);  A: 64x768, W: 768x768
__global__ __launch_bounds__(256) void k_mlp(
    const float* __restrict__ A, const float* __restrict__ W,
    const float* __restrict__ bias, float* __restrict__ C, int do_relu)
{
    __shared__ float As[64 * 68];   // [k][n]
    __shared__ float Ws[64 * 68];   // [k][o]
    int ob  = blockIdx.x * 64;
    int tid = threadIdx.x;
    int tx = tid & 15, ty = tid >> 4;
    int n0 = tx * 4, o0 = ty * 4;
    float acc[4][4];
    #pragma unroll
    for (int i = 0; i < 4; i++) {
        float b = bias[ob + o0 + i];
        #pragma unroll
        for (int j = 0; j < 4; j++) acc[i][j] = b;
    }
    for (int kb = 0; kb < DF; kb += 64) {
        __syncthreads();
        for (int f = tid; f < 64 * 64; f += 256) {
            int n = f >> 6, k = f & 63;
            As[k * 68 + n] = A[n * DF + kb + k];
        }
        for (int f = tid; f < 64 * 64; f += 256) {
            int o = f >> 6, k = f & 63;
            Ws[k * 68 + o] = W[(size_t)(ob + o) * DF + kb + k];
        }
        __syncthreads();
        #pragma unroll 4
        for (int k = 0; k < 64; k++) {
            float4 a = *(const float4*)&As[k * 68 + n0];
            float4 w = *(const float4*)&Ws[k * 68 + o0];
            float av[4] = {a.x, a.y, a.z, a.w};
            float wv[4] = {w.x, w.y, w.z, w.w};
            #pragma unroll
            for (int i = 0; i < 4; i++)
                #pragma unroll
                for (int j = 0; j < 4; j++)
                    acc[i][j] += wv[i] * av[j];
        }
    }
    #pragma unroll
    for (int i = 0; i < 4; i++)
        #pragma unroll
        for (int j = 0; j < 4; j++) {
            float v = acc[i][j];
            if (do_relu) v = fmaxf(v, 0.f);
            C[(n0 + j) * DF + ob + o0 + i] = v;
        }
}

__global__ void k_final(const float* __restrict__ Wf, const float* __restrict__ bf)
{
    int idx = blockIdx.x * 64 + threadIdx.x;
    if (idx >= NB * NCLS) return;
    int n = idx / NCLS, c = idx % NCLS;
    float s = bf[c];
    for (int k = 0; k < DF; k++) s += g_x2[n * DF + k] * Wf[c * DF + k];
    g_logit[n * NCLS + c] = s;
}

__global__ void k_out(float* __restrict__ out)
{
    size_t idx = (size_t)blockIdx.x * 256 + threadIdx.x;
    const size_t LOGN = (size_t)NB * LSEQ * NCLS;        // 49152
    const size_t TOT  = LOGN + (size_t)NB * LSEQ * DF;   // + 12582912
    if (idx >= TOT) return;
    if (idx < LOGN) {
        int c  = (int)(idx % NCLS);
        int nl = (int)(idx / NCLS);
        int n  = nl >> 8;
        out[idx] = g_logit[n * NCLS + c];
    } else {
        size_t r = idx - LOGN;
        int d  = (int)(r % DF);
        int nl = (int)(r / DF);
        int n  = nl >> 8;
        out[idx] = g_pooled[n * DF + d];
    }
}

// =============================================================================
extern "C" void kernel_launch(void* const* d_in, const int* in_sizes, int n_in,
                              void* d_out, int out_size)
{
    const int*   sentence = (const int*)d_in[0];
    const int*   aspect   = (const int*)d_in[1];
    const int*   text_len = (const int*)d_in[2];
    const float* emb      = (const float*)d_in[3];
    const float* w_ih_f   = (const float*)d_in[4];
    const float* w_hh_f   = (const float*)d_in[5];
    const float* b_ih_f   = (const float*)d_in[6];
    const float* b_hh_f   = (const float*)d_in[7];
    const float* w_ih_b   = (const float*)d_in[8];
    const float* w_hh_b   = (const float*)d_in[9];
    const float* b_ih_b   = (const float*)d_in[10];
    const float* b_hh_b   = (const float*)d_in[11];
    const float* W1       = (const float*)d_in[12];
    const float* b1       = (const float*)d_in[13];
    const float* W2       = (const float*)d_in[14];
    const float* b2       = (const float*)d_in[15];
    const float* Wf       = (const float*)d_in[16];
    const float* bf       = (const float*)d_in[17];
    float* out = (float*)d_out;

    float *xg_s, *xg_a, *feat, *afeat, *pooled, *x1, *x2;
    cudaGetSymbolAddress((void**)&xg_s,   g_xg_s);
    cudaGetSymbolAddress((void**)&xg_a,   g_xg_a);
    cudaGetSymbolAddress((void**)&feat,   g_feat);
    cudaGetSymbolAddress((void**)&afeat,  g_afeat);
    cudaGetSymbolAddress((void**)&pooled, g_pooled);
    cudaGetSymbolAddress((void**)&x1,     g_x1);
    cudaGetSymbolAddress((void**)&x2,     g_x2);

    cudaFuncSetAttribute(k_gemm_xg, cudaFuncAttributeMaxDynamicSharedMemorySize, SMEM_XG);
    cudaFuncSetAttribute(k_lstm,    cudaFuncAttributeMaxDynamicSharedMemorySize, SMEM_LSTM);

    k_gemm_xg<<<dim3(LSEQ + LA, 24), 256, SMEM_XG>>>(
        sentence, aspect, emb, w_ih_f, w_ih_b,
        b_ih_f, b_hh_f, b_ih_b, b_hh_b, xg_s, xg_a);

    // shift ncu's fixed capture window (-s 5 -c 1) onto k_lstm
    k_nop<<<1, 32>>>();
    k_nop<<<1, 32>>>();

    k_lstm<<<128, 256, SMEM_LSTM>>>(xg_s, feat, xg_a, afeat, w_hh_f, w_hh_b);

    k_aspmean<<<192, 256>>>();
    k_dot<<<LSEQ, 256>>>();
    k_softmax<<<NB, 256>>>(text_len);
    k_pooled<<<192, 256>>>();

    k_mlp<<<12, 256>>>(pooled, W1, b1, x1, 1);
    k_mlp<<<12, 256>>>(x1,     W2, b2, x2, 1);
    k_final<<<3, 64>>>(Wf, bf);

    size_t tot = (size_t)NB * LSEQ * NCLS + (size_t)NB * LSEQ * DF;
    k_out<<<(unsigned)((tot + 255) / 256), 256>>>(out);
}